// round 10
// baseline (speedup 1.0000x reference)
#include <cuda_runtime.h>

#define BB 64
#define SS 512
#define HH 768
#define TT 4
#define TSTART 2
#define TSTOP 3

// output offsets (float32 elements)
#define OFF_ISQA_PRED 0
#define OFF_CRF       64
#define OFF_LOSS1     32832
#define OFF_LOSS2     32833
#define OFF_TAGS      32834
#define OFF_ISQA      65602

#define NCH 16
#define CHL 32

__device__ float g_feats[BB * SS * TT];
__device__ float g_cls[BB * 2];
__device__ float g_Z[BB];
__device__ float g_gold[BB];
__device__ unsigned int g_zcnt;   // zero-init; reset by loss block each run

// ---------------------------------------------------------------------------
// K1: blocks 0..2047 : feats rows (2 rows per warp, low-reg for occupancy)
//     blocks 2048..2055 : cls logits (one warp per batch)
// ---------------------------------------------------------------------------
__global__ void __launch_bounds__(256, 6)
feats_cls_kernel(const float* __restrict__ emb,
                 const float* __restrict__ crf_W,
                 const float* __restrict__ crf_b,
                 const float* __restrict__ fc2_W,
                 const float* __restrict__ fc2_b) {
    if (blockIdx.x < 2048) {
        __shared__ float sW[TT * HH];
        __shared__ float sb[TT];
        for (int i = threadIdx.x; i < TT * HH; i += 256) sW[i] = crf_W[i];
        if (threadIdx.x < TT) sb[threadIdx.x] = crf_b[threadIdx.x];
        __syncthreads();

        int warp = (blockIdx.x * 256 + threadIdx.x) >> 5;  // 0..16383
        int lane = threadIdx.x & 31;
        int r0 = warp * 2;            // even -> both rows in same batch
        int b = r0 >> 9;
        int s = r0 & 511;
        const float4* e0 = (const float4*)(emb + (long)(b * 513 + s + 1) * HH);
        const float4* e1 = (const float4*)(emb + (long)(b * 513 + s + 2) * HH);
        const float4* W4 = (const float4*)sW;

        float acc0[4] = {0.f, 0.f, 0.f, 0.f};
        float acc1[4] = {0.f, 0.f, 0.f, 0.f};
#pragma unroll
        for (int c = 0; c < 6; ++c) {
            int h4 = c * 32 + lane;
            float4 ea = e0[h4];
            float4 eb = e1[h4];
#pragma unroll
            for (int t = 0; t < 4; ++t) {
                float4 w = W4[t * 192 + h4];
                acc0[t] += ea.x * w.x + ea.y * w.y + ea.z * w.z + ea.w * w.w;
                acc1[t] += eb.x * w.x + eb.y * w.y + eb.z * w.z + eb.w * w.w;
            }
        }
#pragma unroll
        for (int t = 0; t < 4; ++t)
#pragma unroll
            for (int off = 16; off > 0; off >>= 1) {
                acc0[t] += __shfl_xor_sync(0xFFFFFFFFu, acc0[t], off);
                acc1[t] += __shfl_xor_sync(0xFFFFFFFFu, acc1[t], off);
            }
        if (lane == 0) {
            float4 o0, o1;
            o0.x = acc0[0] + sb[0]; o0.y = acc0[1] + sb[1];
            o0.z = acc0[2] + sb[2]; o0.w = acc0[3] + sb[3];
            o1.x = acc1[0] + sb[0]; o1.y = acc1[1] + sb[1];
            o1.z = acc1[2] + sb[2]; o1.w = acc1[3] + sb[3];
            ((float4*)g_feats)[r0]     = o0;
            ((float4*)g_feats)[r0 + 1] = o1;
        }
    } else {
        int warp = threadIdx.x >> 5;
        int lane = threadIdx.x & 31;
        int b = (blockIdx.x - 2048) * 8 + warp;
        const float4* e4 = (const float4*)(emb + (long)b * 513 * HH);
        const float4* wa = (const float4*)fc2_W;
        const float4* wb = (const float4*)(fc2_W + HH);
        float a0 = 0.f, a1 = 0.f;
#pragma unroll
        for (int i = lane; i < 192; i += 32) {
            float4 e = e4[i];
            float4 x = wa[i];
            float4 y = wb[i];
            a0 += e.x * x.x + e.y * x.y + e.z * x.z + e.w * x.w;
            a1 += e.x * y.x + e.y * y.y + e.z * y.z + e.w * y.w;
        }
#pragma unroll
        for (int off = 16; off > 0; off >>= 1) {
            a0 += __shfl_xor_sync(0xFFFFFFFFu, a0, off);
            a1 += __shfl_xor_sync(0xFFFFFFFFu, a1, off);
        }
        if (lane == 0) {
            g_cls[b * 2 + 0] = a0 + fc2_b[0];
            g_cls[b * 2 + 1] = a1 + fc2_b[1];
        }
    }
}

// ---------------------------------------------------------------------------
// K2: 65 blocks x 256 threads.
//   blocks 0..63 : one batch each.
//     warp 0 / tid 0 : scalar 4-state Viterbi scan (FFMA-imm adds, rt=1 on
//                      fma pipe), publishes chunk progress to smem.
//     warps 1-3      : Z chunk scan + combine + gold + tags (named barrier).
//     warp 4         : backpointer recompute chasing scan progress (hidden).
//     then all       : map-composition backtrace.
//   block 64     : loss block; spins on g_zcnt.
// ---------------------------------------------------------------------------
__global__ void __launch_bounds__(256, 1)
crf_kernel(const int* __restrict__ labels,
           const float* __restrict__ trans,
           const int* __restrict__ isqa,
           float* __restrict__ out) {
    __shared__ __align__(16) float sf[SS * TT];   // feats (log)      8 KB
    __shared__ __align__(16) float Dv[SS * TT];   // delta vectors    8 KB
    __shared__ unsigned int bps[SS];              // backpointers     2 KB
    __shared__ float Ml[NCH * 16];                // Z chunk results  1 KB
    __shared__ float st[16];                      // transitions
    __shared__ float gr[1];
    __shared__ unsigned int Fc[16];
    __shared__ int btag[16];
    __shared__ int ltag_s;
    __shared__ int prog;                          // last completed chunk

    int tid = threadIdx.x;

    if (blockIdx.x < 64) {
        int b = blockIdx.x;

        // ---- stage ----
        const float4* fg = (const float4*)(g_feats + (long)b * SS * TT);
        float4* sf4 = (float4*)sf;
        for (int i = tid; i < 512; i += 256) sf4[i] = fg[i];
        if (tid < 16) st[tid] = trans[tid];
        if (tid == 16) prog = -1;
        __syncthreads();

        if (tid == 0) {
            // ======== scalar Viterbi scan ========
            float Ta[16];
#pragma unroll
            for (int i = 0; i < 16; ++i) Ta[i] = st[i];

            float d0 = sf[0] + Ta[TSTART * 4 + 0];
            float d1 = sf[1] + Ta[TSTART * 4 + 1];
            float d2 = sf[2] + Ta[TSTART * 4 + 2];
            float d3 = sf[3] + Ta[TSTART * 4 + 3];
            float4* D4 = (float4*)Dv;
            const float4* s4 = (const float4*)sf;
            D4[0] = make_float4(d0, d1, d2, d3);

#pragma unroll 8
            for (int t = 1; t < SS; ++t) {
                float4 f = s4[t];
                // __fmaf_rn(x,1.0f,y) == x+y bit-exactly (single rounding);
                // compiles to FFMA-imm (rt_SMSP=1 vs FADD's 2).
                float a0 = __fmaf_rn(d0, 1.0f, Ta[0]);
                float a1 = __fmaf_rn(d1, 1.0f, Ta[4]);
                float a2 = __fmaf_rn(d2, 1.0f, Ta[8]);
                float a3 = __fmaf_rn(d3, 1.0f, Ta[12]);
                float b0 = __fmaf_rn(d0, 1.0f, Ta[1]);
                float b1 = __fmaf_rn(d1, 1.0f, Ta[5]);
                float b2 = __fmaf_rn(d2, 1.0f, Ta[9]);
                float b3 = __fmaf_rn(d3, 1.0f, Ta[13]);
                float c0 = __fmaf_rn(d0, 1.0f, Ta[2]);
                float c1 = __fmaf_rn(d1, 1.0f, Ta[6]);
                float c2 = __fmaf_rn(d2, 1.0f, Ta[10]);
                float c3 = __fmaf_rn(d3, 1.0f, Ta[14]);
                float e0 = __fmaf_rn(d0, 1.0f, Ta[3]);
                float e1 = __fmaf_rn(d1, 1.0f, Ta[7]);
                float e2 = __fmaf_rn(d2, 1.0f, Ta[11]);
                float e3 = __fmaf_rn(d3, 1.0f, Ta[15]);
                float n0 = __fmaf_rn(fmaxf(fmaxf(a0, a1), fmaxf(a2, a3)), 1.0f, f.x);
                float n1 = __fmaf_rn(fmaxf(fmaxf(b0, b1), fmaxf(b2, b3)), 1.0f, f.y);
                float n2 = __fmaf_rn(fmaxf(fmaxf(c0, c1), fmaxf(c2, c3)), 1.0f, f.z);
                float n3 = __fmaf_rn(fmaxf(fmaxf(e0, e1), fmaxf(e2, e3)), 1.0f, f.w);
                d0 = n0; d1 = n1; d2 = n2; d3 = n3;
                D4[t] = make_float4(d0, d1, d2, d3);
                if ((t & 31) == 31) {
                    __threadfence_block();
                    *(volatile int*)&prog = t >> 5;   // chunk t>>5 complete
                }
            }
            float q0 = d0 + Ta[3],  q1 = d1 + Ta[7];
            float q2 = d2 + Ta[11], q3 = d3 + Ta[15];
            float md = q0;
            int tg = 0;
            if (q1 > md) { md = q1; tg = 1; }
            if (q2 > md) { md = q2; tg = 2; }
            if (q3 > md) { md = q3; tg = 3; }
            ltag_s = tg;
            out[OFF_CRF + b * SS + (SS - 1)] = (float)tg;
        } else if (tid >= 32 && tid < 128) {
            // ======== Z crew: warps 1-3 (SMSP 1-3), named barrier 1 ========
            if (tid >= 96) {
                // gold + tags (warp 3)
                float gold = 0.f;
                for (int s = tid - 96; s < SS; s += 32) {
                    int tg = labels[b * 513 + 1 + s];
                    gold += sf[s * 4 + tg];
                    out[OFF_TAGS + b * SS + s] = (float)tg;
                    if (s < SS - 1) {
                        int tg2 = labels[b * 513 + 2 + s];
                        gold += st[tg * 4 + tg2];
                    }
                }
#pragma unroll
                for (int off = 16; off > 0; off >>= 1)
                    gold += __shfl_xor_sync(0xFFFFFFFFu, gold, off);
                if (tid == 96) gr[0] = gold;
            }

            int zt = tid - 32;   // 0..95; chunk workers are zt 0..60
            if (zt < 61) {
                float eW[16];
#pragma unroll
                for (int i = 0; i < 16; ++i) eW[i] = __expf(st[i]);

                int c, tbase, k = 0;
                float A0, A1, A2, A3, base = 0.f;
                if (zt == 0) {
                    c = 0; tbase = 0;
                    A0 = __expf(sf[0]) * eW[TSTART * 4 + 0];
                    A1 = __expf(sf[1]) * eW[TSTART * 4 + 1];
                    A2 = __expf(sf[2]) * eW[TSTART * 4 + 2];
                    A3 = __expf(sf[3]) * eW[TSTART * 4 + 3];
                } else {
                    c = 1 + (zt - 1) / 4;
                    k = (zt - 1) & 3;
                    tbase = c * CHL;
                    A0 = (k == 0) ? 1.f : 0.f;
                    A1 = (k == 1) ? 1.f : 0.f;
                    A2 = (k == 2) ? 1.f : 0.f;
                    A3 = (k == 3) ? 1.f : 0.f;
                }
                const float4* sfv4 = (const float4*)sf;
                for (int i = 0; i < CHL; ++i) {
                    int t = tbase + i;
                    if (!(zt == 0 && i == 0)) {
                        float4 fv = sfv4[t];
                        float ex = __expf(fv.x), ey = __expf(fv.y);
                        float ez = __expf(fv.z), ew = __expf(fv.w);
                        float n0 = (A0 * eW[0] + A1 * eW[4] + A2 * eW[8]  + A3 * eW[12]) * ex;
                        float n1 = (A0 * eW[1] + A1 * eW[5] + A2 * eW[9]  + A3 * eW[13]) * ey;
                        float n2 = (A0 * eW[2] + A1 * eW[6] + A2 * eW[10] + A3 * eW[14]) * ez;
                        float n3 = (A0 * eW[3] + A1 * eW[7] + A2 * eW[11] + A3 * eW[15]) * ew;
                        A0 = n0; A1 = n1; A2 = n2; A3 = n3;
                    }
                    if ((i & 7) == 7) {
                        float s = A0 + A1 + A2 + A3;
                        float inv = __fdividef(1.f, s);
                        base += __logf(s);
                        A0 *= inv; A1 *= inv; A2 *= inv; A3 *= inv;
                    }
                }
                Ml[c * 16 + k * 4 + 0] = fmaxf(base + __logf(A0), -1e30f);
                Ml[c * 16 + k * 4 + 1] = fmaxf(base + __logf(A1), -1e30f);
                Ml[c * 16 + k * 4 + 2] = fmaxf(base + __logf(A2), -1e30f);
                Ml[c * 16 + k * 4 + 3] = fmaxf(base + __logf(A3), -1e30f);
            }
            asm volatile("bar.sync 1, 96;" ::: "memory");

            if (tid == 32) {
                float v0 = Ml[0], v1 = Ml[1], v2 = Ml[2], v3 = Ml[3];
                for (int c = 1; c < NCH; ++c) {
                    const float* M = Ml + c * 16;
                    float n[4];
#pragma unroll
                    for (int j = 0; j < 4; ++j) {
                        float s0 = v0 + M[0 * 4 + j];
                        float s1 = v1 + M[1 * 4 + j];
                        float s2 = v2 + M[2 * 4 + j];
                        float s3 = v3 + M[3 * 4 + j];
                        float m = fmaxf(fmaxf(s0, s1), fmaxf(s2, s3));
                        n[j] = m + __logf(__expf(s0 - m) + __expf(s1 - m) +
                                          __expf(s2 - m) + __expf(s3 - m));
                    }
                    v0 = n[0]; v1 = n[1]; v2 = n[2]; v3 = n[3];
                }
                float s0 = v0 + st[0 * 4 + TSTOP];
                float s1 = v1 + st[1 * 4 + TSTOP];
                float s2 = v2 + st[2 * 4 + TSTOP];
                float s3 = v3 + st[3 * 4 + TSTOP];
                float m = fmaxf(fmaxf(s0, s1), fmaxf(s2, s3));
                g_Z[b] = m + __logf(__expf(s0 - m) + __expf(s1 - m) +
                                    __expf(s2 - m) + __expf(s3 - m));

                int t0 = labels[b * 513 + 1];
                int tl = labels[b * 513 + 512];
                g_gold[b] = gr[0] + st[TSTART * 4 + t0] + st[tl * 4 + TSTOP];

                __threadfence();
                atomicAdd(&g_zcnt, 1u);
            }
        } else if (tid >= 128 && tid < 160) {
            // ======== bp warp (warp 4): chase the scan, fill bps ========
            int lane = tid - 128;
            const float4* D4r = (const float4*)Dv;
            for (int c = 0; c < NCH; ++c) {
                while (*(volatile int*)&prog < c) __nanosleep(64);
                asm volatile("" ::: "memory");
                __threadfence_block();   // acquire: Dv writes visible
                int t = c * CHL + lane;
                if (t >= 1) {
                    float4 dp = D4r[t - 1];
                    unsigned w = 0;
#pragma unroll
                    for (int j = 0; j < 4; ++j) {
                        float s0 = dp.x + st[0 * 4 + j];
                        float s1 = dp.y + st[1 * 4 + j];
                        float s2 = dp.z + st[2 * 4 + j];
                        float s3 = dp.w + st[3 * 4 + j];
                        float m01 = fmaxf(s0, s1);
                        float m23 = fmaxf(s2, s3);
                        int b01 = (s1 > s0) ? 1 : 0;
                        int b23 = (s3 > s2) ? 3 : 2;
                        int bp = (m23 > m01) ? b23 : b01;
                        w |= (unsigned)bp << (8 * j);
                    }
                    bps[t] = w;
                }
            }
        }
        __syncthreads();   // scan + Z + bps complete

        // ---- backtrace: map composition over 16 chunks ----
        if (tid < 16) {
            int c = tid;
            int tstart = (c == 0) ? 1 : (c * CHL);
            int tend = c * CHL + 31;
            unsigned F = 0x3210u;
            for (int t = tend; t >= tstart; --t) {
                unsigned g = __byte_perm(bps[t], 0u, F);
                F = (g & 3u) | ((g >> 4) & 0x30u) | ((g >> 8) & 0x300u) |
                    ((g >> 12) & 0x3000u);
            }
            Fc[c] = F;
        }
        __syncthreads();
        if (tid == 0) {
            int tg = ltag_s;
            btag[15] = tg;
            for (int c = 15; c >= 1; --c) {
                tg = (int)((Fc[c] >> (4 * tg)) & 3u);
                btag[c - 1] = tg;
            }
        }
        __syncthreads();
        if (tid < 16) {
            int c = tid;
            int tstart = (c == 0) ? 1 : (c * CHL);
            int tend = c * CHL + 31;
            int tg = btag[c];
            for (int t = tend; t >= tstart; --t) {
                tg = (int)((bps[t] >> (8 * tg)) & 3u);
                out[OFF_CRF + b * SS + t - 1] = (float)tg;
            }
        }
    } else {
        // ================= loss block =================
        __shared__ float red1[2], red2[2];
        float r1 = 0.f, r2 = 0.f;
        if (tid < 64) {
            float l0 = g_cls[tid * 2 + 0];
            float l1 = g_cls[tid * 2 + 1];
            out[OFF_ISQA_PRED + tid] = (l1 > l0) ? 1.f : 0.f;
            float m = fmaxf(l0, l1);
            float lse = m + __logf(__expf(l0 - m) + __expf(l1 - m));
            int y = isqa[tid];
            r1 = -((y != 0 ? l1 : l0) - lse);
            out[OFF_ISQA + tid] = (float)y;
        }
        if (tid == 0) {
            while (atomicAdd(&g_zcnt, 0u) < 64u) __nanosleep(128);
        }
        __syncthreads();
        __threadfence();
        if (tid < 64) {
            r2 = g_Z[tid] - g_gold[tid];
#pragma unroll
            for (int off = 16; off > 0; off >>= 1) {
                r1 += __shfl_xor_sync(0xFFFFFFFFu, r1, off);
                r2 += __shfl_xor_sync(0xFFFFFFFFu, r2, off);
            }
            if ((tid & 31) == 0) {
                red1[tid >> 5] = r1;
                red2[tid >> 5] = r2;
            }
        }
        __syncthreads();
        if (tid == 0) {
            out[OFF_LOSS1] = (red1[0] + red1[1]) / (float)BB;
            out[OFF_LOSS2] = (red2[0] + red2[1]) / (float)BB;
            g_zcnt = 0u;  // reset for next graph replay
        }
    }
}

// ---------------------------------------------------------------------------
extern "C" void kernel_launch(void* const* d_in, const int* in_sizes, int n_in,
                              void* d_out, int out_size) {
    const float* emb    = (const float*)d_in[0];
    const int*   labels = (const int*)d_in[1];
    const int*   isqa   = (const int*)d_in[2];
    const float* fc2_W  = (const float*)d_in[3];
    const float* fc2_b  = (const float*)d_in[4];
    const float* crf_W  = (const float*)d_in[5];
    const float* crf_b  = (const float*)d_in[6];
    const float* trans  = (const float*)d_in[7];
    float* out = (float*)d_out;

    feats_cls_kernel<<<2056, 256>>>(emb, crf_W, crf_b, fc2_W, fc2_b);
    crf_kernel<<<65, 256>>>(labels, trans, isqa, out);
}

// round 14
// speedup vs baseline: 1.1493x; 1.1493x over previous
#include <cuda_runtime.h>

#define BB 64
#define SS 512
#define HH 768
#define TT 4
#define TSTART 2
#define TSTOP 3

// output offsets (float32 elements)
#define OFF_ISQA_PRED 0
#define OFF_CRF       64
#define OFF_LOSS1     32832
#define OFF_LOSS2     32833
#define OFF_TAGS      32834
#define OFF_ISQA      65602

#define NCH 16
#define CHL 32

typedef unsigned long long u64;

// packed f32x2 helpers (Blackwell sm_103a). Per-lane IEEE rn -> bit-exact
// equal to two scalar FADDs. mov.b64 pack/unpack is elided by ptxas when the
// halves can live as an aligned register pair.
#define ADD2(o, a, b) \
    asm("add.rn.f32x2 %0, %1, %2;" : "=l"(o) : "l"(a), "l"(b))
#define PK2(o, lo, hi) \
    asm("mov.b64 %0, {%1, %2};" : "=l"(o) : "f"(lo), "f"(hi))
#define UNPK2(lo, hi, v) \
    asm("mov.b64 {%0, %1}, %2;" : "=f"(lo), "=f"(hi) : "l"(v))

__device__ float g_feats[BB * SS * TT];
__device__ float g_cls[BB * 2];
__device__ float g_Z[BB];
__device__ float g_gold[BB];
__device__ unsigned int g_zcnt;   // zero-init; reset by loss block each run

// ---------------------------------------------------------------------------
// K1: blocks 0..2047 : feats rows (2 rows per warp, low-reg for occupancy)
//     blocks 2048..2055 : cls logits (one warp per batch)
// ---------------------------------------------------------------------------
__global__ void __launch_bounds__(256, 6)
feats_cls_kernel(const float* __restrict__ emb,
                 const float* __restrict__ crf_W,
                 const float* __restrict__ crf_b,
                 const float* __restrict__ fc2_W,
                 const float* __restrict__ fc2_b) {
    if (blockIdx.x < 2048) {
        __shared__ float sW[TT * HH];
        __shared__ float sb[TT];
        for (int i = threadIdx.x; i < TT * HH; i += 256) sW[i] = crf_W[i];
        if (threadIdx.x < TT) sb[threadIdx.x] = crf_b[threadIdx.x];
        __syncthreads();

        int warp = (blockIdx.x * 256 + threadIdx.x) >> 5;  // 0..16383
        int lane = threadIdx.x & 31;
        int r0 = warp * 2;            // even -> both rows in same batch
        int b = r0 >> 9;
        int s = r0 & 511;
        const float4* e0 = (const float4*)(emb + (long)(b * 513 + s + 1) * HH);
        const float4* e1 = (const float4*)(emb + (long)(b * 513 + s + 2) * HH);
        const float4* W4 = (const float4*)sW;

        float acc0[4] = {0.f, 0.f, 0.f, 0.f};
        float acc1[4] = {0.f, 0.f, 0.f, 0.f};
#pragma unroll
        for (int c = 0; c < 6; ++c) {
            int h4 = c * 32 + lane;
            float4 ea = e0[h4];
            float4 eb = e1[h4];
#pragma unroll
            for (int t = 0; t < 4; ++t) {
                float4 w = W4[t * 192 + h4];
                acc0[t] += ea.x * w.x + ea.y * w.y + ea.z * w.z + ea.w * w.w;
                acc1[t] += eb.x * w.x + eb.y * w.y + eb.z * w.z + eb.w * w.w;
            }
        }
#pragma unroll
        for (int t = 0; t < 4; ++t)
#pragma unroll
            for (int off = 16; off > 0; off >>= 1) {
                acc0[t] += __shfl_xor_sync(0xFFFFFFFFu, acc0[t], off);
                acc1[t] += __shfl_xor_sync(0xFFFFFFFFu, acc1[t], off);
            }
        if (lane == 0) {
            float4 o0, o1;
            o0.x = acc0[0] + sb[0]; o0.y = acc0[1] + sb[1];
            o0.z = acc0[2] + sb[2]; o0.w = acc0[3] + sb[3];
            o1.x = acc1[0] + sb[0]; o1.y = acc1[1] + sb[1];
            o1.z = acc1[2] + sb[2]; o1.w = acc1[3] + sb[3];
            ((float4*)g_feats)[r0]     = o0;
            ((float4*)g_feats)[r0 + 1] = o1;
        }
    } else {
        int warp = threadIdx.x >> 5;
        int lane = threadIdx.x & 31;
        int b = (blockIdx.x - 2048) * 8 + warp;
        const float4* e4 = (const float4*)(emb + (long)b * 513 * HH);
        const float4* wa = (const float4*)fc2_W;
        const float4* wb = (const float4*)(fc2_W + HH);
        float a0 = 0.f, a1 = 0.f;
#pragma unroll
        for (int i = lane; i < 192; i += 32) {
            float4 e = e4[i];
            float4 x = wa[i];
            float4 y = wb[i];
            a0 += e.x * x.x + e.y * x.y + e.z * x.z + e.w * x.w;
            a1 += e.x * y.x + e.y * y.y + e.z * y.z + e.w * y.w;
        }
#pragma unroll
        for (int off = 16; off > 0; off >>= 1) {
            a0 += __shfl_xor_sync(0xFFFFFFFFu, a0, off);
            a1 += __shfl_xor_sync(0xFFFFFFFFu, a1, off);
        }
        if (lane == 0) {
            g_cls[b * 2 + 0] = a0 + fc2_b[0];
            g_cls[b * 2 + 1] = a1 + fc2_b[1];
        }
    }
}

// ---------------------------------------------------------------------------
// K2: 65 blocks x 128 threads (round-7 structure; one change: packed f32x2
// adds in the scan).
//   blocks 0..63 : one batch each.
//     tid 0          : scalar 4-state Viterbi scan, transition adds as
//                      add.rn.f32x2 pairs (bit-exact), deltas to smem.
//     threads 32..127: Z chunk scan + combine + gold + tags (named barrier).
//     then all 128   : bp recompute (bit-exact) + map-composition backtrace.
//   block 64     : loss block; spins on g_zcnt.
// ---------------------------------------------------------------------------
__global__ void __launch_bounds__(128, 1)
crf_kernel(const int* __restrict__ labels,
           const float* __restrict__ trans,
           const int* __restrict__ isqa,
           float* __restrict__ out) {
    __shared__ __align__(16) float sf[SS * TT];   // feats (log)      8 KB
    __shared__ __align__(16) float Dv[SS * TT];   // delta vectors    8 KB
    __shared__ unsigned int bps[SS];              // backpointers     2 KB
    __shared__ float Ml[NCH * 16];                // Z chunk results  1 KB
    __shared__ float st[16];                      // transitions
    __shared__ float gr[1];
    __shared__ unsigned int Fc[16];
    __shared__ int btag[16];
    __shared__ int ltag_s;

    int tid = threadIdx.x;

    if (blockIdx.x < 64) {
        int b = blockIdx.x;

        // ---- stage ----
        const float4* fg = (const float4*)(g_feats + (long)b * SS * TT);
        float4* sf4 = (float4*)sf;
        for (int i = tid; i < 512; i += 128) sf4[i] = fg[i];
        if (tid < 16) st[tid] = trans[tid];
        __syncthreads();

        if (tid == 0) {
            // ======== scalar Viterbi scan, packed transition adds ========
            float Ta[16];
#pragma unroll
            for (int i = 0; i < 16; ++i) Ta[i] = st[i];

            // packed transition pairs: TP0[j]=(T[0][j],T[1][j]),
            //                          TP1[j]=(T[2][j],T[3][j])
            u64 TP0[4], TP1[4];
#pragma unroll
            for (int j = 0; j < 4; ++j) {
                PK2(TP0[j], Ta[j],     Ta[4 + j]);
                PK2(TP1[j], Ta[8 + j], Ta[12 + j]);
            }

            float d0 = sf[0] + Ta[TSTART * 4 + 0];
            float d1 = sf[1] + Ta[TSTART * 4 + 1];
            float d2 = sf[2] + Ta[TSTART * 4 + 2];
            float d3 = sf[3] + Ta[TSTART * 4 + 3];
            float4* D4 = (float4*)Dv;
            const float4* s4 = (const float4*)sf;
            D4[0] = make_float4(d0, d1, d2, d3);

            u64 d01, d23;
            PK2(d01, d0, d1);
            PK2(d23, d2, d3);

#pragma unroll 8
            for (int t = 1; t < SS; ++t) {
                float4 f = s4[t];
                u64 P0, P1, P2, P3, Q0, Q1, Q2, Q3;
                ADD2(P0, d01, TP0[0]);  ADD2(Q0, d23, TP1[0]);
                ADD2(P1, d01, TP0[1]);  ADD2(Q1, d23, TP1[1]);
                ADD2(P2, d01, TP0[2]);  ADD2(Q2, d23, TP1[2]);
                ADD2(P3, d01, TP0[3]);  ADD2(Q3, d23, TP1[3]);
                // unpack (register-pair halves; movs elided by ptxas)
                float a0, a1, a2, a3, b0, b1, b2, b3;
                float c0, c1, c2, c3, e0, e1, e2, e3;
                UNPK2(a0, a1, P0);  UNPK2(a2, a3, Q0);
                UNPK2(b0, b1, P1);  UNPK2(b2, b3, Q1);
                UNPK2(c0, c1, P2);  UNPK2(c2, c3, Q2);
                UNPK2(e0, e1, P3);  UNPK2(e2, e3, Q3);
                // identical max-tree + add ordering as the passing kernel
                float n0 = fmaxf(fmaxf(a0, a1), fmaxf(a2, a3)) + f.x;
                float n1 = fmaxf(fmaxf(b0, b1), fmaxf(b2, b3)) + f.y;
                float n2 = fmaxf(fmaxf(c0, c1), fmaxf(c2, c3)) + f.z;
                float n3 = fmaxf(fmaxf(e0, e1), fmaxf(e2, e3)) + f.w;
                PK2(d01, n0, n1);
                PK2(d23, n2, n3);
                D4[t] = make_float4(n0, n1, n2, n3);
            }
            UNPK2(d0, d1, d01);
            UNPK2(d2, d3, d23);

            float q0 = d0 + Ta[3],  q1 = d1 + Ta[7];
            float q2 = d2 + Ta[11], q3 = d3 + Ta[15];
            float md = q0;
            int tg = 0;
            if (q1 > md) { md = q1; tg = 1; }
            if (q2 > md) { md = q2; tg = 2; }
            if (q3 > md) { md = q3; tg = 3; }
            ltag_s = tg;
            out[OFF_CRF + b * SS + (SS - 1)] = (float)tg;
        } else if (tid >= 32) {
            // ======== Z crew: threads 32..127, private named barrier 1 ======
            if (tid >= 96) {
                // gold + tags (warp 3: threads 96..127)
                float gold = 0.f;
                for (int s = tid - 96; s < SS; s += 32) {
                    int tg = labels[b * 513 + 1 + s];
                    gold += sf[s * 4 + tg];
                    out[OFF_TAGS + b * SS + s] = (float)tg;
                    if (s < SS - 1) {
                        int tg2 = labels[b * 513 + 2 + s];
                        gold += st[tg * 4 + tg2];
                    }
                }
#pragma unroll
                for (int off = 16; off > 0; off >>= 1)
                    gold += __shfl_xor_sync(0xFFFFFFFFu, gold, off);
                if (tid == 96) gr[0] = gold;
            }

            int zt = tid - 32;   // 0..95; chunk workers are zt 0..60
            if (zt < 61) {
                float eW[16];
#pragma unroll
                for (int i = 0; i < 16; ++i) eW[i] = __expf(st[i]);

                int c, tbase, k = 0;
                float A0, A1, A2, A3, base = 0.f;
                if (zt == 0) {
                    c = 0; tbase = 0;
                    A0 = __expf(sf[0]) * eW[TSTART * 4 + 0];
                    A1 = __expf(sf[1]) * eW[TSTART * 4 + 1];
                    A2 = __expf(sf[2]) * eW[TSTART * 4 + 2];
                    A3 = __expf(sf[3]) * eW[TSTART * 4 + 3];
                } else {
                    c = 1 + (zt - 1) / 4;
                    k = (zt - 1) & 3;
                    tbase = c * CHL;
                    A0 = (k == 0) ? 1.f : 0.f;
                    A1 = (k == 1) ? 1.f : 0.f;
                    A2 = (k == 2) ? 1.f : 0.f;
                    A3 = (k == 3) ? 1.f : 0.f;
                }
                const float4* sfv4 = (const float4*)sf;
                for (int i = 0; i < CHL; ++i) {
                    int t = tbase + i;
                    if (!(zt == 0 && i == 0)) {
                        float4 fv = sfv4[t];
                        float ex = __expf(fv.x), ey = __expf(fv.y);
                        float ez = __expf(fv.z), ew = __expf(fv.w);
                        float n0 = (A0 * eW[0] + A1 * eW[4] + A2 * eW[8]  + A3 * eW[12]) * ex;
                        float n1 = (A0 * eW[1] + A1 * eW[5] + A2 * eW[9]  + A3 * eW[13]) * ey;
                        float n2 = (A0 * eW[2] + A1 * eW[6] + A2 * eW[10] + A3 * eW[14]) * ez;
                        float n3 = (A0 * eW[3] + A1 * eW[7] + A2 * eW[11] + A3 * eW[15]) * ew;
                        A0 = n0; A1 = n1; A2 = n2; A3 = n3;
                    }
                    if ((i & 7) == 7) {
                        float s = A0 + A1 + A2 + A3;
                        float inv = __fdividef(1.f, s);
                        base += __logf(s);
                        A0 *= inv; A1 *= inv; A2 *= inv; A3 *= inv;
                    }
                }
                Ml[c * 16 + k * 4 + 0] = fmaxf(base + __logf(A0), -1e30f);
                Ml[c * 16 + k * 4 + 1] = fmaxf(base + __logf(A1), -1e30f);
                Ml[c * 16 + k * 4 + 2] = fmaxf(base + __logf(A2), -1e30f);
                Ml[c * 16 + k * 4 + 3] = fmaxf(base + __logf(A3), -1e30f);
            }
            asm volatile("bar.sync 1, 96;" ::: "memory");

            if (tid == 32) {
                float v0 = Ml[0], v1 = Ml[1], v2 = Ml[2], v3 = Ml[3];
                for (int c = 1; c < NCH; ++c) {
                    const float* M = Ml + c * 16;
                    float n[4];
#pragma unroll
                    for (int j = 0; j < 4; ++j) {
                        float s0 = v0 + M[0 * 4 + j];
                        float s1 = v1 + M[1 * 4 + j];
                        float s2 = v2 + M[2 * 4 + j];
                        float s3 = v3 + M[3 * 4 + j];
                        float m = fmaxf(fmaxf(s0, s1), fmaxf(s2, s3));
                        n[j] = m + __logf(__expf(s0 - m) + __expf(s1 - m) +
                                          __expf(s2 - m) + __expf(s3 - m));
                    }
                    v0 = n[0]; v1 = n[1]; v2 = n[2]; v3 = n[3];
                }
                float s0 = v0 + st[0 * 4 + TSTOP];
                float s1 = v1 + st[1 * 4 + TSTOP];
                float s2 = v2 + st[2 * 4 + TSTOP];
                float s3 = v3 + st[3 * 4 + TSTOP];
                float m = fmaxf(fmaxf(s0, s1), fmaxf(s2, s3));
                g_Z[b] = m + __logf(__expf(s0 - m) + __expf(s1 - m) +
                                    __expf(s2 - m) + __expf(s3 - m));

                int t0 = labels[b * 513 + 1];
                int tl = labels[b * 513 + 512];
                g_gold[b] = gr[0] + st[TSTART * 4 + t0] + st[tl * 4 + TSTOP];

                __threadfence();
                atomicAdd(&g_zcnt, 1u);
            }
        }
        __syncthreads();   // scan + Z complete

        // ---- parallel backpointer recompute (bit-exact vs scan order) ----
        {
            const float4* D4r = (const float4*)Dv;
            for (int t = 1 + tid; t < SS; t += 128) {
                float4 dp = D4r[t - 1];
                unsigned w = 0;
#pragma unroll
                for (int j = 0; j < 4; ++j) {
                    float s0 = dp.x + st[0 * 4 + j];
                    float s1 = dp.y + st[1 * 4 + j];
                    float s2 = dp.z + st[2 * 4 + j];
                    float s3 = dp.w + st[3 * 4 + j];
                    float m01 = fmaxf(s0, s1);
                    float m23 = fmaxf(s2, s3);
                    int b01 = (s1 > s0) ? 1 : 0;
                    int b23 = (s3 > s2) ? 3 : 2;
                    int bp = (m23 > m01) ? b23 : b01;
                    w |= (unsigned)bp << (8 * j);
                }
                bps[t] = w;
            }
        }
        __syncthreads();

        // ---- backtrace: map composition over 16 chunks ----
        if (tid < 16) {
            int c = tid;
            int tstart = (c == 0) ? 1 : (c * CHL);
            int tend = c * CHL + 31;
            unsigned F = 0x3210u;
            for (int t = tend; t >= tstart; --t) {
                unsigned g = __byte_perm(bps[t], 0u, F);
                F = (g & 3u) | ((g >> 4) & 0x30u) | ((g >> 8) & 0x300u) |
                    ((g >> 12) & 0x3000u);
            }
            Fc[c] = F;
        }
        __syncthreads();
        if (tid == 0) {
            int tg = ltag_s;
            btag[15] = tg;
            for (int c = 15; c >= 1; --c) {
                tg = (int)((Fc[c] >> (4 * tg)) & 3u);
                btag[c - 1] = tg;
            }
        }
        __syncthreads();
        if (tid < 16) {
            int c = tid;
            int tstart = (c == 0) ? 1 : (c * CHL);
            int tend = c * CHL + 31;
            int tg = btag[c];
            for (int t = tend; t >= tstart; --t) {
                tg = (int)((bps[t] >> (8 * tg)) & 3u);
                out[OFF_CRF + b * SS + t - 1] = (float)tg;
            }
        }
    } else {
        // ================= loss block =================
        __shared__ float red1[2], red2[2];
        float r1 = 0.f, r2 = 0.f;
        if (tid < 64) {
            float l0 = g_cls[tid * 2 + 0];
            float l1 = g_cls[tid * 2 + 1];
            out[OFF_ISQA_PRED + tid] = (l1 > l0) ? 1.f : 0.f;
            float m = fmaxf(l0, l1);
            float lse = m + __logf(__expf(l0 - m) + __expf(l1 - m));
            int y = isqa[tid];
            r1 = -((y != 0 ? l1 : l0) - lse);
            out[OFF_ISQA + tid] = (float)y;
        }
        if (tid == 0) {
            while (atomicAdd(&g_zcnt, 0u) < 64u) __nanosleep(128);
        }
        __syncthreads();
        __threadfence();
        if (tid < 64) {
            r2 = g_Z[tid] - g_gold[tid];
#pragma unroll
            for (int off = 16; off > 0; off >>= 1) {
                r1 += __shfl_xor_sync(0xFFFFFFFFu, r1, off);
                r2 += __shfl_xor_sync(0xFFFFFFFFu, r2, off);
            }
            if ((tid & 31) == 0) {
                red1[tid >> 5] = r1;
                red2[tid >> 5] = r2;
            }
        }
        __syncthreads();
        if (tid == 0) {
            out[OFF_LOSS1] = (red1[0] + red1[1]) / (float)BB;
            out[OFF_LOSS2] = (red2[0] + red2[1]) / (float)BB;
            g_zcnt = 0u;  // reset for next graph replay
        }
    }
}

// ---------------------------------------------------------------------------
extern "C" void kernel_launch(void* const* d_in, const int* in_sizes, int n_in,
                              void* d_out, int out_size) {
    const float* emb    = (const float*)d_in[0];
    const int*   labels = (const int*)d_in[1];
    const int*   isqa   = (const int*)d_in[2];
    const float* fc2_W  = (const float*)d_in[3];
    const float* fc2_b  = (const float*)d_in[4];
    const float* crf_W  = (const float*)d_in[5];
    const float* crf_b  = (const float*)d_in[6];
    const float* trans  = (const float*)d_in[7];
    float* out = (float*)d_out;

    feats_cls_kernel<<<2056, 256>>>(emb, crf_W, crf_b, fc2_W, fc2_b);
    crf_kernel<<<65, 128>>>(labels, trans, isqa, out);
}